// round 15
// baseline (speedup 1.0000x reference)
#include <cuda_runtime.h>
#include <cuda_bf16.h>
#include <cuda_fp16.h>
#include <stdint.h>

#define FD   128        // feature dim
#define MAXN 100000     // nodes
#define MAXE 1664000    // edges (1.6M + slack)
#define CHUNK 1024      // elements per scan block
#define TILE_M 128
#define SROW 136        // smem tile row stride in bf16 elems (272B, conflict-free)
#define SROWB (SROW * 2)
#define GEMM_GRID 148

// ---------------------------------------------------------------------------
// Scratch (device globals — no allocation allowed in kernel_launch)
// ---------------------------------------------------------------------------
__device__ float g_dinv[MAXN];
__device__ int   g_cnt  [MAXN];
__device__ int   g_rowptr[MAXN + 1];
__device__ int   g_fill [MAXN];
__device__ int   g_csrc [MAXE];
__device__ int   g_bsum [256];
__device__ int   g_boff [256];
__device__ float g_r1[MAXN], g_r2[MAXN], g_r3[MAXN], g_r4[MAXN];
__device__ float g_za[MAXN], g_zb[MAXN];
// fp16 feature planes: X copy + double-buffered intermediates
__device__ __align__(128) __half g_Xh[(size_t)(MAXN + 256) * FD];
__device__ __align__(128) __half g_Ha[(size_t)(MAXN + 256) * FD];
__device__ __align__(128) __half g_Hb[(size_t)(MAXN + 256) * FD];
__device__ __align__(128) __nv_bfloat16 g_hh[(size_t)(MAXN + 256) * FD];
__device__ __align__(128) __nv_bfloat16 g_hl[(size_t)(MAXN + 256) * FD];
__device__ __align__(128) float g_W22[FD * FD];
__device__ __align__(128) float g_W4 [FD * FD];
__device__ __align__(128) float g_M  [FD * FD];
__device__ __align__(128) __nv_bfloat16 g_Mh[FD * FD];
__device__ __align__(128) __nv_bfloat16 g_Ml[FD * FD];
__device__ float g_uv[4 * FD];   // u1,u2,u3,u4

// ---------------------------------------------------------------------------
// Degree / normalization
// ---------------------------------------------------------------------------
__global__ void k_deg_count(const int* __restrict__ dst, int e) {
    int i = blockIdx.x * blockDim.x + threadIdx.x;
    if (i < e) atomicAdd(&g_cnt[dst[i]], 1);
}

__global__ void k_dinv(int n) {
    int i = blockIdx.x * blockDim.x + threadIdx.x;
    if (i < n) g_dinv[i] = rsqrtf(2.0f + (float)g_cnt[i]);
}

// ---------------------------------------------------------------------------
// 3-pass parallel exclusive scan of g_cnt -> g_rowptr / g_fill
// ---------------------------------------------------------------------------
__global__ void __launch_bounds__(256) k_scan1(int n) {
    const int t = threadIdx.x;
    const int base = blockIdx.x * CHUNK + t * 4;
    int s = 0;
#pragma unroll
    for (int m = 0; m < 4; m++) {
        int i = base + m;
        if (i < n) s += g_cnt[i];
    }
#pragma unroll
    for (int o = 16; o > 0; o >>= 1) s += __shfl_down_sync(0xffffffffu, s, o);
    __shared__ int ws[8];
    if ((t & 31) == 0) ws[t >> 5] = s;
    __syncthreads();
    if (t < 8) {
        int v = ws[t];
#pragma unroll
        for (int o = 4; o > 0; o >>= 1) v += __shfl_down_sync(0xffu, v, o);
        if (t == 0) g_bsum[blockIdx.x] = v;
    }
}

__global__ void __launch_bounds__(256) k_scan2(int nb, int n) {
    __shared__ int sh[256];
    int t = threadIdx.x;
    int v = (t < nb) ? g_bsum[t] : 0;
    sh[t] = v;
    __syncthreads();
#pragma unroll
    for (int o = 1; o < 256; o <<= 1) {
        int u = (t >= o) ? sh[t - o] : 0;
        __syncthreads();
        sh[t] += u;
        __syncthreads();
    }
    g_boff[t] = sh[t] - v;
    if (t == nb - 1) g_rowptr[n] = sh[t];
}

__global__ void __launch_bounds__(256) k_scan3(int n) {
    const int t = threadIdx.x;
    const int lane = t & 31;
    const int warp = t >> 5;
    const int base = blockIdx.x * CHUNK + t * 4;

    int c[4];
    int s = 0;
#pragma unroll
    for (int m = 0; m < 4; m++) {
        int i = base + m;
        c[m] = (i < n) ? g_cnt[i] : 0;
        s += c[m];
    }
    int incl = s;
#pragma unroll
    for (int o = 1; o < 32; o <<= 1) {
        int u = __shfl_up_sync(0xffffffffu, incl, o);
        if (lane >= o) incl += u;
    }
    __shared__ int wtot[8];
    if (lane == 31) wtot[warp] = incl;
    __syncthreads();
    int woff = 0;
#pragma unroll
    for (int w = 0; w < 7; w++)
        if (w < warp) woff += wtot[w];
    int pre = g_boff[blockIdx.x] + woff + incl - s;
#pragma unroll
    for (int m = 0; m < 4; m++) {
        int i = base + m;
        if (i < n) {
            g_rowptr[i] = pre;
            g_fill[i]   = pre;
            pre += c[m];
        }
    }
}

__global__ void k_scatter(const int* __restrict__ src, const int* __restrict__ dst, int e) {
    int i = blockIdx.x * blockDim.x + threadIdx.x;
    if (i < e) {
        int d = dst[i];
        int pos = atomicAdd(&g_fill[d], 1);
        g_csrc[pos] = src[i];
    }
}

// ---------------------------------------------------------------------------
// Grid-parallel 128x128 matmul: C = A*B. grid=16 blocks, 8 rows/block.
// ---------------------------------------------------------------------------
__global__ void __launch_bounds__(256) k_mm128p(const float* __restrict__ A,
                                                const float* __restrict__ B,
                                                float* __restrict__ C) {
    extern __shared__ float sB[];   // [128][128]
    const int tid = threadIdx.x;
    for (int i = tid; i < FD * FD / 4; i += 256)
        ((float4*)sB)[i] = ((const float4*)B)[i];
    __syncthreads();
    const int row  = blockIdx.x * 8 + (tid >> 5);
    const int lane = tid & 31;
    float4 acc = make_float4(0.f, 0.f, 0.f, 0.f);
    const float* arow = A + row * FD;
#pragma unroll 4
    for (int k = 0; k < FD; k++) {
        float a = __ldg(arow + k);
        float4 b = ((const float4*)sB)[k * 32 + lane];
        acc.x = fmaf(a, b.x, acc.x);
        acc.y = fmaf(a, b.y, acc.y);
        acc.z = fmaf(a, b.z, acc.z);
        acc.w = fmaf(a, b.w, acc.w);
    }
    ((float4*)(C + row * FD))[lane] = acc;
}

// Fused bias-vector chain: u1=b2*W2, u2=u1*W2, u3=u2*W2, u4=b1*W4.
__global__ void __launch_bounds__(128) k_uchain(const float* __restrict__ W2,
                                                const float* __restrict__ W4,
                                                const float* __restrict__ b1,
                                                const float* __restrict__ b2,
                                                float* __restrict__ uv) {
    extern __shared__ float sm[];
    float* sW2 = sm;                 // 128*128
    float* sW4 = sm + FD * FD;       // 128*128
    __shared__ float su[FD];
    const int t = threadIdx.x;
    for (int i = t; i < FD * FD / 4; i += 128) {
        ((float4*)sW2)[i] = ((const float4*)W2)[i];
        ((float4*)sW4)[i] = ((const float4*)W4)[i];
    }
    su[t] = b2[t];
    __syncthreads();
#pragma unroll
    for (int rep = 0; rep < 3; rep++) {
        float s = 0.0f;
#pragma unroll 8
        for (int k = 0; k < FD; k++) s = fmaf(su[k], sW2[k * FD + t], s);
        __syncthreads();
        su[t] = s;
        uv[rep * FD + t] = s;
        __syncthreads();
    }
    su[t] = b1[t];
    __syncthreads();
    {
        float s = 0.0f;
#pragma unroll 8
        for (int k = 0; k < FD; k++) s = fmaf(su[k], sW4[k * FD + t], s);
        uv[3 * FD + t] = s;
    }
}

// M[k][n] fp32 -> Mh/Ml[n][k] bf16 (transposed: n rows, k contiguous)
__global__ void __launch_bounds__(256) k_wsplit(const float* __restrict__ W,
                                                __nv_bfloat16* __restrict__ Wh,
                                                __nv_bfloat16* __restrict__ Wl) {
    int i = blockIdx.x * blockDim.x + threadIdx.x;   // i = n*128 + k
    if (i >= FD * FD) return;
    int nn = i >> 7, kk = i & 127;
    float w = W[kk * FD + nn];
    __nv_bfloat16 h = __float2bfloat16_rn(w);
    __nv_bfloat16 l = __float2bfloat16_rn(w - __bfloat162float(h));
    Wh[i] = h;
    Wl[i] = l;
}

// X fp32 -> fp16 plane
__global__ void __launch_bounds__(256) k_xhalf(const float* __restrict__ x, int total4) {
    int i = blockIdx.x * blockDim.x + threadIdx.x;   // float4 index
    if (i >= total4) return;
    float4 v = *(const float4*)(x + (size_t)i * 4);
    __half2 h0 = __floats2half2_rn(v.x, v.y);
    __half2 h1 = __floats2half2_rn(v.z, v.w);
    uint2 p = make_uint2(*(uint32_t*)&h0, *(uint32_t*)&h1);
    *(uint2*)(g_Xh + (size_t)i * 4) = p;
}

// ---------------------------------------------------------------------------
// helpers: fp16 row chunk (8 cols) <-> 8 fp32; bf16 hi/lo split of 8 values
// ---------------------------------------------------------------------------
__device__ __forceinline__ void gather8(const __half* __restrict__ P,
                                        size_t base, int c, float* f) {
    uint4 p = *(const uint4*)(P + base + c);
    const __half2* h = (const __half2*)&p;
#pragma unroll
    for (int i = 0; i < 4; i++) {
        float2 t = __half22float2(h[i]);
        f[2 * i] = t.x; f[2 * i + 1] = t.y;
    }
}

__device__ __forceinline__ void store8(__half* __restrict__ P, size_t base,
                                       int c, const float* f) {
    uint4 p;
    __half2* h = (__half2*)&p;
#pragma unroll
    for (int i = 0; i < 4; i++) h[i] = __floats2half2_rn(f[2 * i], f[2 * i + 1]);
    *(uint4*)(P + base + c) = p;
}

__device__ __forceinline__ void split8(const float* v, uint4& hi, uint4& lo) {
    __nv_bfloat162* hp = (__nv_bfloat162*)&hi;
    __nv_bfloat162* lp = (__nv_bfloat162*)&lo;
#pragma unroll
    for (int i = 0; i < 4; i++) {
        float a = v[2 * i], b = v[2 * i + 1];
        __nv_bfloat16 ha = __float2bfloat16_rn(a);
        __nv_bfloat16 hb = __float2bfloat16_rn(b);
        __nv_bfloat16 la = __float2bfloat16_rn(a - __bfloat162float(ha));
        __nv_bfloat16 lb = __float2bfloat16_rn(b - __bfloat162float(hb));
        hp[i] = __halves2bfloat162(ha, hb);
        lp[i] = __halves2bfloat162(la, lb);
    }
}

// ---------------------------------------------------------------------------
// Linear aggregation passes: TWO nodes per warp (16 lanes x 16B per row),
// 8 neighbor rows in flight per unroll iteration (deep MLP).
// MODE 0 (PRE): In = Xh, src-weight dinv; out fp16; scalar chain z0=dinv
// MODE 1 (MID): In fp16; out fp16; scalar chain z_{k-1}
// MODE 2 (FIN): In fp16; out = bf16 hi/lo split (g_hh/g_hl)
// ---------------------------------------------------------------------------
template <int MODE>
__global__ void __launch_bounds__(256) k_aggH(const __half* __restrict__ In,
                                              const float* __restrict__ zin,
                                              __half* __restrict__ Out,
                                              float* __restrict__ rk,
                                              float* __restrict__ zout, int n) {
    const int node = blockIdx.x * 16 + (threadIdx.x >> 4);   // half-warp -> node
    const int lane = threadIdx.x & 15;
    const int c = lane << 3;                                  // 8 fp16 cols
    const bool act = (node < n);

    const int beg = act ? g_rowptr[node] : 0;
    const int end = act ? g_rowptr[node + 1] : 0;
    const float dv = act ? g_dinv[node] : 0.0f;

    float acc[8];
    if (act) {
        gather8(In, (size_t)node * FD, c, acc);
        const float sw = (MODE == 0) ? 2.0f * dv : 2.0f;
#pragma unroll
        for (int i = 0; i < 8; i++) acc[i] *= sw;
    } else {
#pragma unroll
        for (int i = 0; i < 8; i++) acc[i] = 0.0f;
    }
    float sacc = (MODE < 2 && act) ? 2.0f * __ldg(zin + node) : 0.0f;

    int j = beg;
    // 8-deep unroll: 8 independent row gathers in flight per half-warp
    for (; j + 7 < end; j += 8) {
        int si[8];
#pragma unroll
        for (int q = 0; q < 8; q++) si[q] = __ldg(g_csrc + j + q);
        float v[8][8];
#pragma unroll
        for (int q = 0; q < 8; q++)
            gather8(In, (size_t)si[q] * FD, c, v[q]);
        if (MODE == 0) {
            float w[8];
#pragma unroll
            for (int q = 0; q < 8; q++) w[q] = __ldg(zin + si[q]);
#pragma unroll
            for (int i = 0; i < 8; i++) {
                float s = acc[i];
#pragma unroll
                for (int q = 0; q < 8; q++) s = fmaf(w[q], v[q][i], s);
                acc[i] = s;
            }
#pragma unroll
            for (int q = 0; q < 8; q++) sacc += w[q];
        } else {
#pragma unroll
            for (int i = 0; i < 8; i++) {
                float s01 = v[0][i] + v[1][i];
                float s23 = v[2][i] + v[3][i];
                float s45 = v[4][i] + v[5][i];
                float s67 = v[6][i] + v[7][i];
                acc[i] += (s01 + s23) + (s45 + s67);
            }
            if (MODE == 1) {
#pragma unroll
                for (int q = 0; q < 8; q++) sacc += __ldg(zin + si[q]);
            }
        }
    }
    // 4-deep remainder
    for (; j + 3 < end; j += 4) {
        int s0 = __ldg(g_csrc + j);
        int s1 = __ldg(g_csrc + j + 1);
        int s2 = __ldg(g_csrc + j + 2);
        int s3 = __ldg(g_csrc + j + 3);
        float v0[8], v1[8], v2[8], v3[8];
        gather8(In, (size_t)s0 * FD, c, v0);
        gather8(In, (size_t)s1 * FD, c, v1);
        gather8(In, (size_t)s2 * FD, c, v2);
        gather8(In, (size_t)s3 * FD, c, v3);
        if (MODE == 0) {
            float w0 = __ldg(zin + s0), w1 = __ldg(zin + s1);
            float w2 = __ldg(zin + s2), w3 = __ldg(zin + s3);
#pragma unroll
            for (int i = 0; i < 8; i++)
                acc[i] = fmaf(w0, v0[i], fmaf(w1, v1[i],
                          fmaf(w2, v2[i], fmaf(w3, v3[i], acc[i]))));
            sacc += w0 + w1 + w2 + w3;
        } else {
#pragma unroll
            for (int i = 0; i < 8; i++)
                acc[i] += (v0[i] + v1[i]) + (v2[i] + v3[i]);
            if (MODE == 1)
                sacc += __ldg(zin + s0) + __ldg(zin + s1)
                      + __ldg(zin + s2) + __ldg(zin + s3);
        }
    }
    for (; j < end; j++) {
        int s = __ldg(g_csrc + j);
        float v[8];
        gather8(In, (size_t)s * FD, c, v);
        if (MODE == 0) {
            float w = __ldg(zin + s);
#pragma unroll
            for (int i = 0; i < 8; i++) acc[i] = fmaf(w, v[i], acc[i]);
            sacc += w;
        } else {
#pragma unroll
            for (int i = 0; i < 8; i++) acc[i] += v[i];
            if (MODE == 1) sacc += __ldg(zin + s);
        }
    }

    if (!act) return;

    if (MODE == 2) {
#pragma unroll
        for (int i = 0; i < 8; i++) acc[i] *= dv;
        uint4 hi, lo;
        split8(acc, hi, lo);
        *(uint4*)(g_hh + (size_t)node * FD + c) = hi;
        *(uint4*)(g_hl + (size_t)node * FD + c) = lo;
    } else {
        const float s2 = dv * dv;
#pragma unroll
        for (int i = 0; i < 8; i++) acc[i] *= s2;
        store8(Out, (size_t)node * FD, c, acc);
        if (lane == 0) {
            rk[node]   = dv * sacc;
            zout[node] = s2 * sacc;
        }
    }
}

// ---------------------------------------------------------------------------
// Persistent HMMA GEMM with cp.async double buffering.
//   out = (Y @ M) + sum_k r_k (x) u_k + b2,  Y@M via bf16 3-term split
// ---------------------------------------------------------------------------
__device__ __forceinline__ uint32_t smem_to_u32(const void* p) {
    uint32_t a;
    asm("{ .reg .u64 t; cvta.to.shared.u64 t, %1; cvt.u32.u64 %0, t; }"
        : "=r"(a) : "l"(p));
    return a;
}

__device__ __forceinline__ void ldsm_x4(uint32_t& r0, uint32_t& r1,
                                        uint32_t& r2, uint32_t& r3, uint32_t addr) {
    asm volatile("ldmatrix.sync.aligned.m8n8.x4.shared.b16 {%0,%1,%2,%3}, [%4];"
                 : "=r"(r0), "=r"(r1), "=r"(r2), "=r"(r3) : "r"(addr));
}

__device__ __forceinline__ void mma16816(float* c, uint32_t a0, uint32_t a1,
                                         uint32_t a2, uint32_t a3,
                                         uint32_t b0, uint32_t b1) {
    asm volatile(
        "mma.sync.aligned.m16n8k16.row.col.f32.bf16.bf16.f32 "
        "{%0,%1,%2,%3}, {%4,%5,%6,%7}, {%8,%9}, {%0,%1,%2,%3};"
        : "+f"(c[0]), "+f"(c[1]), "+f"(c[2]), "+f"(c[3])
        : "r"(a0), "r"(a1), "r"(a2), "r"(a3), "r"(b0), "r"(b1));
}

__device__ __forceinline__ void cp_tile(uint32_t dstbase, const __nv_bfloat16* g) {
    const char* gp = (const char*)g;
    const int tid = threadIdx.x;
#pragma unroll
    for (int i = 0; i < 8; i++) {
        int gi = tid + i * 256;
        int r  = gi >> 4;
        int ch = gi & 15;
        uint32_t dst = dstbase + (uint32_t)r * SROWB + (uint32_t)ch * 16;
        asm volatile("cp.async.cg.shared.global [%0], [%1], 16;"
                     :: "r"(dst), "l"(gp + (size_t)gi * 16));
    }
}

#define CP_COMMIT() asm volatile("cp.async.commit_group;" ::: "memory")
template <int N>
__device__ __forceinline__ void cp_wait() {
    asm volatile("cp.async.wait_group %0;" :: "n"(N) : "memory");
}

#define TILEB  (128 * SROWB)
#define SM_WH  0
#define SM_WL  TILEB
#define SM_A0H (2 * TILEB)
#define SM_A0L (3 * TILEB)
#define SM_A1H (4 * TILEB)
#define SM_A1L (5 * TILEB)
#define SM_UVEC (6 * TILEB)
#define SM_TOTAL (6 * TILEB + 5 * FD * 4)

__global__ void __launch_bounds__(256, 1)
k_gemm_mma(const __nv_bfloat16* __restrict__ Ah,
           const __nv_bfloat16* __restrict__ Al,
           const __nv_bfloat16* __restrict__ Wh,
           const __nv_bfloat16* __restrict__ Wl,
           float* __restrict__ Out,
           const float* __restrict__ R1, const float* __restrict__ R2,
           const float* __restrict__ R3, const float* __restrict__ R4,
           const float* __restrict__ uv, const float* __restrict__ b2, int n) {
    extern __shared__ char smem[];
    const uint32_t sb = smem_to_u32(smem);
    float* su = (float*)(smem + SM_UVEC);   // u1,u2,u3,u4,b2 (5 x 128)
    const int tid  = threadIdx.x;
    const int lane = tid & 31;
    const int wr0  = (tid >> 5) << 4;
    const int ntiles = (n + TILE_M - 1) / TILE_M;

    if (tid < FD) {
#pragma unroll
        for (int t = 0; t < 4; t++) su[t * FD + tid] = uv[t * FD + tid];
        su[4 * FD + tid] = b2[tid];
    }

    const uint32_t aoff = (uint32_t)(wr0 + (lane & 15)) * SROWB
                        + (uint32_t)((lane >> 4) << 4);
    const uint32_t boff = (uint32_t)(((lane >> 4) << 3) + (lane & 7)) * SROWB
                        + (uint32_t)(((lane >> 3) & 1) << 4);

    int t0 = blockIdx.x;
    if (t0 >= ntiles) return;

    cp_tile(sb + SM_WH, Wh);
    cp_tile(sb + SM_WL, Wl);
    cp_tile(sb + SM_A0H, Ah + (size_t)t0 * TILE_M * FD);
    cp_tile(sb + SM_A0L, Al + (size_t)t0 * TILE_M * FD);
    CP_COMMIT();

    int stage = 0;
    for (int t = t0; t < ntiles; t += GEMM_GRID) {
        const int tn = t + GEMM_GRID;
        if (tn < ntiles) {
            const uint32_t dh = sb + (stage ? SM_A0H : SM_A1H);
            const uint32_t dl = sb + (stage ? SM_A0L : SM_A1L);
            cp_tile(dh, Ah + (size_t)tn * TILE_M * FD);
            cp_tile(dl, Al + (size_t)tn * TILE_M * FD);
            CP_COMMIT();
            cp_wait<1>();
        } else {
            cp_wait<0>();
        }
        __syncthreads();

        const uint32_t sAH = sb + (stage ? SM_A1H : SM_A0H);
        const uint32_t sAL = sb + (stage ? SM_A1L : SM_A0L);

        float acc[16][4];
#pragma unroll
        for (int q = 0; q < 16; q++)
#pragma unroll
            for (int j = 0; j < 4; j++) acc[q][j] = 0.0f;

#pragma unroll
        for (int term = 0; term < 3; term++) {
            const uint32_t aBase = aoff + ((term == 2) ? sAL : sAH);
            const uint32_t bBase = boff + sb + ((term == 1) ? SM_WL : SM_WH);

            uint32_t a[8][4];
#pragma unroll
            for (int ks = 0; ks < 8; ks++)
                ldsm_x4(a[ks][0], a[ks][1], a[ks][2], a[ks][3], aBase + ks * 32);

#pragma unroll
            for (int nt = 0; nt < 8; nt++) {
                const uint32_t bnt = bBase + (uint32_t)nt * 16 * SROWB;
#pragma unroll
                for (int ks = 0; ks < 8; ks++) {
                    uint32_t b0, b1, b2r, b3;
                    ldsm_x4(b0, b1, b2r, b3, bnt + ks * 32);
                    mma16816(acc[nt * 2],     a[ks][0], a[ks][1], a[ks][2], a[ks][3], b0, b1);
                    mma16816(acc[nt * 2 + 1], a[ks][0], a[ks][1], a[ks][2], a[ks][3], b2r, b3);
                }
            }
        }

        const int row0 = t * TILE_M;
        const int r0g = row0 + wr0 + (lane >> 2);
        const int r1g = r0g + 8;
        float ra[4] = {0.f, 0.f, 0.f, 0.f}, rb[4] = {0.f, 0.f, 0.f, 0.f};
        if (r0g < n) { ra[0] = R1[r0g]; ra[1] = R2[r0g]; ra[2] = R3[r0g]; ra[3] = R4[r0g]; }
        if (r1g < n) { rb[0] = R1[r1g]; rb[1] = R2[r1g]; rb[2] = R3[r1g]; rb[3] = R4[r1g]; }
        const int cbase = (lane & 3) << 1;
#pragma unroll
        for (int q = 0; q < 16; q++) {
            const int col = q * 8 + cbase;
            float e00 = acc[q][0], e01 = acc[q][1];
            float e10 = acc[q][2], e11 = acc[q][3];
#pragma unroll
            for (int k = 0; k < 4; k++) {
                float u0 = su[k * FD + col], u1 = su[k * FD + col + 1];
                e00 = fmaf(ra[k], u0, e00); e01 = fmaf(ra[k], u1, e01);
                e10 = fmaf(rb[k], u0, e10); e11 = fmaf(rb[k], u1, e11);
            }
            e00 += su[4 * FD + col]; e01 += su[4 * FD + col + 1];
            e10 += su[4 * FD + col]; e11 += su[4 * FD + col + 1];
            if (r0g < n)
                *(float2*)(Out + (size_t)r0g * FD + col) = make_float2(e00, e01);
            if (r1g < n)
                *(float2*)(Out + (size_t)r1g * FD + col) = make_float2(e10, e11);
        }

        __syncthreads();
        stage ^= 1;
    }
}

// ---------------------------------------------------------------------------
// Launcher
// ---------------------------------------------------------------------------
extern "C" void kernel_launch(void* const* d_in, const int* in_sizes, int n_in,
                              void* d_out, int out_size) {
    const float* x  = (const float*)d_in[0];
    const int*   ei = (const int*)  d_in[1];
    const float* W1 = (const float*)d_in[2];
    const float* b1 = (const float*)d_in[3];
    const float* W2 = (const float*)d_in[4];
    const float* b2 = (const float*)d_in[5];
    float* out = (float*)d_out;

    const int n = in_sizes[0] / FD;
    const int e = in_sizes[1] / 2;
    const int* src = ei;
    const int* dst = ei + e;

    float *W22, *W4, *M, *uv, *r1, *r2, *r3, *r4, *za, *zb, *dinvp;
    int* cntp;
    __half *Xh, *Ha, *Hb;
    __nv_bfloat16 *hh, *hl, *Mh, *Ml;
    cudaGetSymbolAddress((void**)&Xh,  g_Xh);
    cudaGetSymbolAddress((void**)&Ha,  g_Ha);
    cudaGetSymbolAddress((void**)&Hb,  g_Hb);
    cudaGetSymbolAddress((void**)&W22, g_W22);
    cudaGetSymbolAddress((void**)&W4,  g_W4);
    cudaGetSymbolAddress((void**)&M,   g_M);
    cudaGetSymbolAddress((void**)&uv,  g_uv);
    cudaGetSymbolAddress((void**)&r1,  g_r1);
    cudaGetSymbolAddress((void**)&r2,  g_r2);
    cudaGetSymbolAddress((void**)&r3,  g_r3);
    cudaGetSymbolAddress((void**)&r4,  g_r4);
    cudaGetSymbolAddress((void**)&za,  g_za);
    cudaGetSymbolAddress((void**)&zb,  g_zb);
    cudaGetSymbolAddress((void**)&dinvp, g_dinv);
    cudaGetSymbolAddress((void**)&cntp, g_cnt);
    cudaGetSymbolAddress((void**)&hh,  g_hh);
    cudaGetSymbolAddress((void**)&hl,  g_hl);
    cudaGetSymbolAddress((void**)&Mh,  g_Mh);
    cudaGetSymbolAddress((void**)&Ml,  g_Ml);

    cudaFuncSetAttribute(k_gemm_mma, cudaFuncAttributeMaxDynamicSharedMemorySize,
                         SM_TOTAL);
    cudaFuncSetAttribute(k_mm128p, cudaFuncAttributeMaxDynamicSharedMemorySize,
                         FD * FD * 4);
    cudaFuncSetAttribute(k_uchain, cudaFuncAttributeMaxDynamicSharedMemorySize,
                         2 * FD * FD * 4);

    const int nb = (n + CHUNK - 1) / CHUNK;
    const int nhb = (n + 15) / 16;   // 16 nodes per 256-thread block

    // degree + normalization + CSR build
    cudaMemsetAsync(cntp, 0, (size_t)n * sizeof(int));
    k_deg_count<<<(e + 255) / 256, 256>>>(dst, e);
    k_dinv     <<<(n + 255) / 256, 256>>>(n);
    k_scan1    <<<nb, 256>>>(n);
    k_scan2    <<<1, 256>>>(nb, n);
    k_scan3    <<<nb, 256>>>(n);
    k_scatter  <<<(e + 255) / 256, 256>>>(src, dst, e);

    // weight chain (grid-parallel): W22 = W2^2, W4 = W22^2, M = W1*W4; split M
    k_mm128p<<<16, 256, FD * FD * 4>>>(W2,  W2,  W22);
    k_mm128p<<<16, 256, FD * FD * 4>>>(W22, W22, W4);
    k_mm128p<<<16, 256, FD * FD * 4>>>(W1,  W4,  M);
    k_wsplit<<<(FD * FD + 255) / 256, 256>>>(M, Mh, Ml);

    // fused bias-vector chain
    k_uchain<<<1, 128, 2 * FD * FD * 4>>>(W2, W4, b1, b2, uv);

    // X -> fp16 plane
    k_xhalf<<<(n * (FD / 4) + 255) / 256, 256>>>(x, n * (FD / 4));

    // 5 aggregation passes: Xh -> Ha -> Hb -> Ha -> Hb -> (hh,hl)
    k_aggH<0><<<nhb, 256>>>(Xh, dinvp, Ha, r1, za, n);
    k_aggH<1><<<nhb, 256>>>(Ha, za,    Hb, r2, zb, n);
    k_aggH<1><<<nhb, 256>>>(Hb, zb,    Ha, r3, za, n);
    k_aggH<1><<<nhb, 256>>>(Ha, za,    Hb, r4, zb, n);
    k_aggH<2><<<nhb, 256>>>(Hb, nullptr, nullptr, nullptr, nullptr, n);

    // final GEMM: out = Y*M + r1*u1 + r2*u2 + r3*u3 + r4*u4 + b2
    k_gemm_mma<<<GEMM_GRID, 256, SM_TOTAL>>>(hh, hl, Mh, Ml, out,
                                             r1, r2, r3, r4, uv, b2, n);
}

// round 16
// speedup vs baseline: 1.0290x; 1.0290x over previous
#include <cuda_runtime.h>
#include <cuda_bf16.h>
#include <cuda_fp16.h>
#include <stdint.h>

#define FD   128        // feature dim
#define MAXN 100000     // nodes
#define MAXE 1664000    // edges (1.6M + slack)
#define CHUNK 1024      // elements per scan block
#define TILE_M 128
#define SROW 136        // smem tile row stride in bf16 elems (272B, conflict-free)
#define SROWB (SROW * 2)
#define GEMM_GRID 148

// ---------------------------------------------------------------------------
// Scratch (device globals — no allocation allowed in kernel_launch)
// ---------------------------------------------------------------------------
__device__ float g_dinv[MAXN];
__device__ int   g_cnt  [MAXN];
__device__ int   g_rowptr[MAXN + 1];
__device__ int   g_fill [MAXN];
__device__ int   g_csrc [MAXE];
__device__ int   g_bsum [256];
__device__ int   g_boff [256];
__device__ float g_r1[MAXN], g_r2[MAXN], g_r3[MAXN], g_r4[MAXN];
__device__ float g_za[MAXN], g_zb[MAXN];
// fp16 feature planes: X copy + double-buffered intermediates
__device__ __align__(128) __half g_Xh[(size_t)(MAXN + 256) * FD];
__device__ __align__(128) __half g_Ha[(size_t)(MAXN + 256) * FD];
__device__ __align__(128) __half g_Hb[(size_t)(MAXN + 256) * FD];
__device__ __align__(128) __nv_bfloat16 g_hh[(size_t)(MAXN + 256) * FD];
__device__ __align__(128) __nv_bfloat16 g_hl[(size_t)(MAXN + 256) * FD];
__device__ __align__(128) float g_W22[FD * FD];
__device__ __align__(128) float g_W4 [FD * FD];
__device__ __align__(128) float g_M  [FD * FD];
__device__ __align__(128) __nv_bfloat16 g_Mh[FD * FD];
__device__ __align__(128) __nv_bfloat16 g_Ml[FD * FD];
__device__ float g_uv[4 * FD];   // u1,u2,u3,u4

// ---------------------------------------------------------------------------
// Degree counting
// ---------------------------------------------------------------------------
__global__ void k_deg_count(const int* __restrict__ dst, int e) {
    int i = blockIdx.x * blockDim.x + threadIdx.x;
    if (i < e) atomicAdd(&g_cnt[dst[i]], 1);
}

// ---------------------------------------------------------------------------
// 3-pass parallel exclusive scan of g_cnt -> g_rowptr / g_fill.
// Pass 1 also computes g_dinv (fused; both read g_cnt).
// ---------------------------------------------------------------------------
__global__ void __launch_bounds__(256) k_scan1(int n) {
    const int t = threadIdx.x;
    const int base = blockIdx.x * CHUNK + t * 4;
    int s = 0;
#pragma unroll
    for (int m = 0; m < 4; m++) {
        int i = base + m;
        if (i < n) {
            int cv = g_cnt[i];
            s += cv;
            g_dinv[i] = rsqrtf(2.0f + (float)cv);
        }
    }
#pragma unroll
    for (int o = 16; o > 0; o >>= 1) s += __shfl_down_sync(0xffffffffu, s, o);
    __shared__ int ws[8];
    if ((t & 31) == 0) ws[t >> 5] = s;
    __syncthreads();
    if (t < 8) {
        int v = ws[t];
#pragma unroll
        for (int o = 4; o > 0; o >>= 1) v += __shfl_down_sync(0xffu, v, o);
        if (t == 0) g_bsum[blockIdx.x] = v;
    }
}

__global__ void __launch_bounds__(256) k_scan2(int nb, int n) {
    __shared__ int sh[256];
    int t = threadIdx.x;
    int v = (t < nb) ? g_bsum[t] : 0;
    sh[t] = v;
    __syncthreads();
#pragma unroll
    for (int o = 1; o < 256; o <<= 1) {
        int u = (t >= o) ? sh[t - o] : 0;
        __syncthreads();
        sh[t] += u;
        __syncthreads();
    }
    g_boff[t] = sh[t] - v;
    if (t == nb - 1) g_rowptr[n] = sh[t];
}

__global__ void __launch_bounds__(256) k_scan3(int n) {
    const int t = threadIdx.x;
    const int lane = t & 31;
    const int warp = t >> 5;
    const int base = blockIdx.x * CHUNK + t * 4;

    int c[4];
    int s = 0;
#pragma unroll
    for (int m = 0; m < 4; m++) {
        int i = base + m;
        c[m] = (i < n) ? g_cnt[i] : 0;
        s += c[m];
    }
    int incl = s;
#pragma unroll
    for (int o = 1; o < 32; o <<= 1) {
        int u = __shfl_up_sync(0xffffffffu, incl, o);
        if (lane >= o) incl += u;
    }
    __shared__ int wtot[8];
    if (lane == 31) wtot[warp] = incl;
    __syncthreads();
    int woff = 0;
#pragma unroll
    for (int w = 0; w < 7; w++)
        if (w < warp) woff += wtot[w];
    int pre = g_boff[blockIdx.x] + woff + incl - s;
#pragma unroll
    for (int m = 0; m < 4; m++) {
        int i = base + m;
        if (i < n) {
            g_rowptr[i] = pre;
            g_fill[i]   = pre;
            pre += c[m];
        }
    }
}

__global__ void k_scatter(const int* __restrict__ src, const int* __restrict__ dst, int e) {
    int i = blockIdx.x * blockDim.x + threadIdx.x;
    if (i < e) {
        int d = dst[i];
        int pos = atomicAdd(&g_fill[d], 1);
        g_csrc[pos] = src[i];
    }
}

// ---------------------------------------------------------------------------
// Grid-parallel 128x128 matmul: C = A*B. grid=16 blocks, 8 rows/block.
// ---------------------------------------------------------------------------
__global__ void __launch_bounds__(256) k_mm128p(const float* __restrict__ A,
                                                const float* __restrict__ B,
                                                float* __restrict__ C) {
    extern __shared__ float sB[];   // [128][128]
    const int tid = threadIdx.x;
    for (int i = tid; i < FD * FD / 4; i += 256)
        ((float4*)sB)[i] = ((const float4*)B)[i];
    __syncthreads();
    const int row  = blockIdx.x * 8 + (tid >> 5);
    const int lane = tid & 31;
    float4 acc = make_float4(0.f, 0.f, 0.f, 0.f);
    const float* arow = A + row * FD;
#pragma unroll 4
    for (int k = 0; k < FD; k++) {
        float a = __ldg(arow + k);
        float4 b = ((const float4*)sB)[k * 32 + lane];
        acc.x = fmaf(a, b.x, acc.x);
        acc.y = fmaf(a, b.y, acc.y);
        acc.z = fmaf(a, b.z, acc.z);
        acc.w = fmaf(a, b.w, acc.w);
    }
    ((float4*)(C + row * FD))[lane] = acc;
}

// Fused bias-vector chain: u1=b2*W2, u2=u1*W2, u3=u2*W2, u4=b1*W4.
__global__ void __launch_bounds__(128) k_uchain(const float* __restrict__ W2,
                                                const float* __restrict__ W4,
                                                const float* __restrict__ b1,
                                                const float* __restrict__ b2,
                                                float* __restrict__ uv) {
    extern __shared__ float sm[];
    float* sW2 = sm;                 // 128*128
    float* sW4 = sm + FD * FD;       // 128*128
    __shared__ float su[FD];
    const int t = threadIdx.x;
    for (int i = t; i < FD * FD / 4; i += 128) {
        ((float4*)sW2)[i] = ((const float4*)W2)[i];
        ((float4*)sW4)[i] = ((const float4*)W4)[i];
    }
    su[t] = b2[t];
    __syncthreads();
#pragma unroll
    for (int rep = 0; rep < 3; rep++) {
        float s = 0.0f;
#pragma unroll 8
        for (int k = 0; k < FD; k++) s = fmaf(su[k], sW2[k * FD + t], s);
        __syncthreads();
        su[t] = s;
        uv[rep * FD + t] = s;
        __syncthreads();
    }
    su[t] = b1[t];
    __syncthreads();
    {
        float s = 0.0f;
#pragma unroll 8
        for (int k = 0; k < FD; k++) s = fmaf(su[k], sW4[k * FD + t], s);
        uv[3 * FD + t] = s;
    }
}

// M[k][n] fp32 -> Mh/Ml[n][k] bf16 (transposed: n rows, k contiguous)
__global__ void __launch_bounds__(256) k_wsplit(const float* __restrict__ W,
                                                __nv_bfloat16* __restrict__ Wh,
                                                __nv_bfloat16* __restrict__ Wl) {
    int i = blockIdx.x * blockDim.x + threadIdx.x;   // i = n*128 + k
    if (i >= FD * FD) return;
    int nn = i >> 7, kk = i & 127;
    float w = W[kk * FD + nn];
    __nv_bfloat16 h = __float2bfloat16_rn(w);
    __nv_bfloat16 l = __float2bfloat16_rn(w - __bfloat162float(h));
    Wh[i] = h;
    Wl[i] = l;
}

// X fp32 -> fp16 plane
__global__ void __launch_bounds__(256) k_xhalf(const float* __restrict__ x, int total4) {
    int i = blockIdx.x * blockDim.x + threadIdx.x;   // float4 index
    if (i >= total4) return;
    float4 v = *(const float4*)(x + (size_t)i * 4);
    __half2 h0 = __floats2half2_rn(v.x, v.y);
    __half2 h1 = __floats2half2_rn(v.z, v.w);
    uint2 p = make_uint2(*(uint32_t*)&h0, *(uint32_t*)&h1);
    *(uint2*)(g_Xh + (size_t)i * 4) = p;
}

// ---------------------------------------------------------------------------
// helpers: fp16 row chunk (8 cols) <-> 8 fp32; bf16 hi/lo split of 8 values
// ---------------------------------------------------------------------------
__device__ __forceinline__ void gather8(const __half* __restrict__ P,
                                        size_t base, int c, float* f) {
    uint4 p = *(const uint4*)(P + base + c);
    const __half2* h = (const __half2*)&p;
#pragma unroll
    for (int i = 0; i < 4; i++) {
        float2 t = __half22float2(h[i]);
        f[2 * i] = t.x; f[2 * i + 1] = t.y;
    }
}

__device__ __forceinline__ void store8(__half* __restrict__ P, size_t base,
                                       int c, const float* f) {
    uint4 p;
    __half2* h = (__half2*)&p;
#pragma unroll
    for (int i = 0; i < 4; i++) h[i] = __floats2half2_rn(f[2 * i], f[2 * i + 1]);
    *(uint4*)(P + base + c) = p;
}

__device__ __forceinline__ void split8(const float* v, uint4& hi, uint4& lo) {
    __nv_bfloat162* hp = (__nv_bfloat162*)&hi;
    __nv_bfloat162* lp = (__nv_bfloat162*)&lo;
#pragma unroll
    for (int i = 0; i < 4; i++) {
        float a = v[2 * i], b = v[2 * i + 1];
        __nv_bfloat16 ha = __float2bfloat16_rn(a);
        __nv_bfloat16 hb = __float2bfloat16_rn(b);
        __nv_bfloat16 la = __float2bfloat16_rn(a - __bfloat162float(ha));
        __nv_bfloat16 lb = __float2bfloat16_rn(b - __bfloat162float(hb));
        hp[i] = __halves2bfloat162(ha, hb);
        lp[i] = __halves2bfloat162(la, lb);
    }
}

// ---------------------------------------------------------------------------
// Linear aggregation passes: TWO nodes per warp (16 lanes x 16B per row),
// 4-deep register gather + L1 prefetch two quads ahead (no register cost).
// MODE 0 (PRE): In = Xh, src-weight dinv; out fp16; scalar chain z0=dinv
// MODE 1 (MID): In fp16; out fp16; scalar chain z_{k-1}
// MODE 2 (FIN): In fp16; out = bf16 hi/lo split (g_hh/g_hl)
// ---------------------------------------------------------------------------
template <int MODE>
__global__ void __launch_bounds__(256) k_aggH(const __half* __restrict__ In,
                                              const float* __restrict__ zin,
                                              __half* __restrict__ Out,
                                              float* __restrict__ rk,
                                              float* __restrict__ zout, int n) {
    const int node = blockIdx.x * 16 + (threadIdx.x >> 4);   // half-warp -> node
    const int lane = threadIdx.x & 15;
    const int c = lane << 3;                                  // 8 fp16 cols
    const bool act = (node < n);

    const int beg = act ? g_rowptr[node] : 0;
    const int end = act ? g_rowptr[node + 1] : 0;
    const float dv = act ? g_dinv[node] : 0.0f;

    float acc[8];
    if (act) {
        gather8(In, (size_t)node * FD, c, acc);
        const float sw = (MODE == 0) ? 2.0f * dv : 2.0f;
#pragma unroll
        for (int i = 0; i < 8; i++) acc[i] *= sw;
    } else {
#pragma unroll
        for (int i = 0; i < 8; i++) acc[i] = 0.0f;
    }
    float sacc = (MODE < 2 && act) ? 2.0f * __ldg(zin + node) : 0.0f;

    int j = beg;
    for (; j + 3 < end; j += 4) {
        // L1 prefetch two quads ahead: lanes 0-7 each cover one 128B half-line
        if (j + 11 < end && lane < 8) {
            int ps = __ldg(g_csrc + j + 8 + (lane >> 1));
            const __half* pa = In + (size_t)ps * FD + ((lane & 1) << 6);
            asm volatile("prefetch.global.L1 [%0];" :: "l"(pa));
        }
        int s0 = __ldg(g_csrc + j);
        int s1 = __ldg(g_csrc + j + 1);
        int s2 = __ldg(g_csrc + j + 2);
        int s3 = __ldg(g_csrc + j + 3);
        float v0[8], v1[8], v2[8], v3[8];
        gather8(In, (size_t)s0 * FD, c, v0);
        gather8(In, (size_t)s1 * FD, c, v1);
        gather8(In, (size_t)s2 * FD, c, v2);
        gather8(In, (size_t)s3 * FD, c, v3);
        if (MODE == 0) {
            float w0 = __ldg(zin + s0), w1 = __ldg(zin + s1);
            float w2 = __ldg(zin + s2), w3 = __ldg(zin + s3);
#pragma unroll
            for (int i = 0; i < 8; i++)
                acc[i] = fmaf(w0, v0[i], fmaf(w1, v1[i],
                          fmaf(w2, v2[i], fmaf(w3, v3[i], acc[i]))));
            sacc += w0 + w1 + w2 + w3;
        } else {
#pragma unroll
            for (int i = 0; i < 8; i++)
                acc[i] += (v0[i] + v1[i]) + (v2[i] + v3[i]);
            if (MODE == 1)
                sacc += __ldg(zin + s0) + __ldg(zin + s1)
                      + __ldg(zin + s2) + __ldg(zin + s3);
        }
    }
    for (; j < end; j++) {
        int s = __ldg(g_csrc + j);
        float v[8];
        gather8(In, (size_t)s * FD, c, v);
        if (MODE == 0) {
            float w = __ldg(zin + s);
#pragma unroll
            for (int i = 0; i < 8; i++) acc[i] = fmaf(w, v[i], acc[i]);
            sacc += w;
        } else {
#pragma unroll
            for (int i = 0; i < 8; i++) acc[i] += v[i];
            if (MODE == 1) sacc += __ldg(zin + s);
        }
    }

    if (!act) return;

    if (MODE == 2) {
#pragma unroll
        for (int i = 0; i < 8; i++) acc[i] *= dv;
        uint4 hi, lo;
        split8(acc, hi, lo);
        *(uint4*)(g_hh + (size_t)node * FD + c) = hi;
        *(uint4*)(g_hl + (size_t)node * FD + c) = lo;
    } else {
        const float s2 = dv * dv;
#pragma unroll
        for (int i = 0; i < 8; i++) acc[i] *= s2;
        store8(Out, (size_t)node * FD, c, acc);
        if (lane == 0) {
            rk[node]   = dv * sacc;
            zout[node] = s2 * sacc;
        }
    }
}

// ---------------------------------------------------------------------------
// Persistent HMMA GEMM with cp.async double buffering.
//   out = (Y @ M) + sum_k r_k (x) u_k + b2,  Y@M via bf16 3-term split
// ---------------------------------------------------------------------------
__device__ __forceinline__ uint32_t smem_to_u32(const void* p) {
    uint32_t a;
    asm("{ .reg .u64 t; cvta.to.shared.u64 t, %1; cvt.u32.u64 %0, t; }"
        : "=r"(a) : "l"(p));
    return a;
}

__device__ __forceinline__ void ldsm_x4(uint32_t& r0, uint32_t& r1,
                                        uint32_t& r2, uint32_t& r3, uint32_t addr) {
    asm volatile("ldmatrix.sync.aligned.m8n8.x4.shared.b16 {%0,%1,%2,%3}, [%4];"
                 : "=r"(r0), "=r"(r1), "=r"(r2), "=r"(r3) : "r"(addr));
}

__device__ __forceinline__ void mma16816(float* c, uint32_t a0, uint32_t a1,
                                         uint32_t a2, uint32_t a3,
                                         uint32_t b0, uint32_t b1) {
    asm volatile(
        "mma.sync.aligned.m16n8k16.row.col.f32.bf16.bf16.f32 "
        "{%0,%1,%2,%3}, {%4,%5,%6,%7}, {%8,%9}, {%0,%1,%2,%3};"
        : "+f"(c[0]), "+f"(c[1]), "+f"(c[2]), "+f"(c[3])
        : "r"(a0), "r"(a1), "r"(a2), "r"(a3), "r"(b0), "r"(b1));
}

__device__ __forceinline__ void cp_tile(uint32_t dstbase, const __nv_bfloat16* g) {
    const char* gp = (const char*)g;
    const int tid = threadIdx.x;
#pragma unroll
    for (int i = 0; i < 8; i++) {
        int gi = tid + i * 256;
        int r  = gi >> 4;
        int ch = gi & 15;
        uint32_t dst = dstbase + (uint32_t)r * SROWB + (uint32_t)ch * 16;
        asm volatile("cp.async.cg.shared.global [%0], [%1], 16;"
                     :: "r"(dst), "l"(gp + (size_t)gi * 16));
    }
}

#define CP_COMMIT() asm volatile("cp.async.commit_group;" ::: "memory")
template <int N>
__device__ __forceinline__ void cp_wait() {
    asm volatile("cp.async.wait_group %0;" :: "n"(N) : "memory");
}

#define TILEB  (128 * SROWB)
#define SM_WH  0
#define SM_WL  TILEB
#define SM_A0H (2 * TILEB)
#define SM_A0L (3 * TILEB)
#define SM_A1H (4 * TILEB)
#define SM_A1L (5 * TILEB)
#define SM_UVEC (6 * TILEB)
#define SM_TOTAL (6 * TILEB + 5 * FD * 4)

__global__ void __launch_bounds__(256, 1)
k_gemm_mma(const __nv_bfloat16* __restrict__ Ah,
           const __nv_bfloat16* __restrict__ Al,
           const __nv_bfloat16* __restrict__ Wh,
           const __nv_bfloat16* __restrict__ Wl,
           float* __restrict__ Out,
           const float* __restrict__ R1, const float* __restrict__ R2,
           const float* __restrict__ R3, const float* __restrict__ R4,
           const float* __restrict__ uv, const float* __restrict__ b2, int n) {
    extern __shared__ char smem[];
    const uint32_t sb = smem_to_u32(smem);
    float* su = (float*)(smem + SM_UVEC);   // u1,u2,u3,u4,b2 (5 x 128)
    const int tid  = threadIdx.x;
    const int lane = tid & 31;
    const int wr0  = (tid >> 5) << 4;
    const int ntiles = (n + TILE_M - 1) / TILE_M;

    if (tid < FD) {
#pragma unroll
        for (int t = 0; t < 4; t++) su[t * FD + tid] = uv[t * FD + tid];
        su[4 * FD + tid] = b2[tid];
    }

    const uint32_t aoff = (uint32_t)(wr0 + (lane & 15)) * SROWB
                        + (uint32_t)((lane >> 4) << 4);
    const uint32_t boff = (uint32_t)(((lane >> 4) << 3) + (lane & 7)) * SROWB
                        + (uint32_t)(((lane >> 3) & 1) << 4);

    int t0 = blockIdx.x;
    if (t0 >= ntiles) return;

    cp_tile(sb + SM_WH, Wh);
    cp_tile(sb + SM_WL, Wl);
    cp_tile(sb + SM_A0H, Ah + (size_t)t0 * TILE_M * FD);
    cp_tile(sb + SM_A0L, Al + (size_t)t0 * TILE_M * FD);
    CP_COMMIT();

    int stage = 0;
    for (int t = t0; t < ntiles; t += GEMM_GRID) {
        const int tn = t + GEMM_GRID;
        if (tn < ntiles) {
            const uint32_t dh = sb + (stage ? SM_A0H : SM_A1H);
            const uint32_t dl = sb + (stage ? SM_A0L : SM_A1L);
            cp_tile(dh, Ah + (size_t)tn * TILE_M * FD);
            cp_tile(dl, Al + (size_t)tn * TILE_M * FD);
            CP_COMMIT();
            cp_wait<1>();
        } else {
            cp_wait<0>();
        }
        __syncthreads();

        const uint32_t sAH = sb + (stage ? SM_A1H : SM_A0H);
        const uint32_t sAL = sb + (stage ? SM_A1L : SM_A0L);

        float acc[16][4];
#pragma unroll
        for (int q = 0; q < 16; q++)
#pragma unroll
            for (int j = 0; j < 4; j++) acc[q][j] = 0.0f;

#pragma unroll
        for (int term = 0; term < 3; term++) {
            const uint32_t aBase = aoff + ((term == 2) ? sAL : sAH);
            const uint32_t bBase = boff + sb + ((term == 1) ? SM_WL : SM_WH);

            uint32_t a[8][4];
#pragma unroll
            for (int ks = 0; ks < 8; ks++)
                ldsm_x4(a[ks][0], a[ks][1], a[ks][2], a[ks][3], aBase + ks * 32);

#pragma unroll
            for (int nt = 0; nt < 8; nt++) {
                const uint32_t bnt = bBase + (uint32_t)nt * 16 * SROWB;
#pragma unroll
                for (int ks = 0; ks < 8; ks++) {
                    uint32_t b0, b1, b2r, b3;
                    ldsm_x4(b0, b1, b2r, b3, bnt + ks * 32);
                    mma16816(acc[nt * 2],     a[ks][0], a[ks][1], a[ks][2], a[ks][3], b0, b1);
                    mma16816(acc[nt * 2 + 1], a[ks][0], a[ks][1], a[ks][2], a[ks][3], b2r, b3);
                }
            }
        }

        const int row0 = t * TILE_M;
        const int r0g = row0 + wr0 + (lane >> 2);
        const int r1g = r0g + 8;
        float ra[4] = {0.f, 0.f, 0.f, 0.f}, rb[4] = {0.f, 0.f, 0.f, 0.f};
        if (r0g < n) { ra[0] = R1[r0g]; ra[1] = R2[r0g]; ra[2] = R3[r0g]; ra[3] = R4[r0g]; }
        if (r1g < n) { rb[0] = R1[r1g]; rb[1] = R2[r1g]; rb[2] = R3[r1g]; rb[3] = R4[r1g]; }
        const int cbase = (lane & 3) << 1;
#pragma unroll
        for (int q = 0; q < 16; q++) {
            const int col = q * 8 + cbase;
            float e00 = acc[q][0], e01 = acc[q][1];
            float e10 = acc[q][2], e11 = acc[q][3];
#pragma unroll
            for (int k = 0; k < 4; k++) {
                float u0 = su[k * FD + col], u1 = su[k * FD + col + 1];
                e00 = fmaf(ra[k], u0, e00); e01 = fmaf(ra[k], u1, e01);
                e10 = fmaf(rb[k], u0, e10); e11 = fmaf(rb[k], u1, e11);
            }
            e00 += su[4 * FD + col]; e01 += su[4 * FD + col + 1];
            e10 += su[4 * FD + col]; e11 += su[4 * FD + col + 1];
            if (r0g < n)
                *(float2*)(Out + (size_t)r0g * FD + col) = make_float2(e00, e01);
            if (r1g < n)
                *(float2*)(Out + (size_t)r1g * FD + col) = make_float2(e10, e11);
        }

        __syncthreads();
        stage ^= 1;
    }
}

// ---------------------------------------------------------------------------
// Launcher
// ---------------------------------------------------------------------------
extern "C" void kernel_launch(void* const* d_in, const int* in_sizes, int n_in,
                              void* d_out, int out_size) {
    const float* x  = (const float*)d_in[0];
    const int*   ei = (const int*)  d_in[1];
    const float* W1 = (const float*)d_in[2];
    const float* b1 = (const float*)d_in[3];
    const float* W2 = (const float*)d_in[4];
    const float* b2 = (const float*)d_in[5];
    float* out = (float*)d_out;

    const int n = in_sizes[0] / FD;
    const int e = in_sizes[1] / 2;
    const int* src = ei;
    const int* dst = ei + e;

    float *W22, *W4, *M, *uv, *r1, *r2, *r3, *r4, *za, *zb, *dinvp;
    int* cntp;
    __half *Xh, *Ha, *Hb;
    __nv_bfloat16 *hh, *hl, *Mh, *Ml;
    cudaGetSymbolAddress((void**)&Xh,  g_Xh);
    cudaGetSymbolAddress((void**)&Ha,  g_Ha);
    cudaGetSymbolAddress((void**)&Hb,  g_Hb);
    cudaGetSymbolAddress((void**)&W22, g_W22);
    cudaGetSymbolAddress((void**)&W4,  g_W4);
    cudaGetSymbolAddress((void**)&M,   g_M);
    cudaGetSymbolAddress((void**)&uv,  g_uv);
    cudaGetSymbolAddress((void**)&r1,  g_r1);
    cudaGetSymbolAddress((void**)&r2,  g_r2);
    cudaGetSymbolAddress((void**)&r3,  g_r3);
    cudaGetSymbolAddress((void**)&r4,  g_r4);
    cudaGetSymbolAddress((void**)&za,  g_za);
    cudaGetSymbolAddress((void**)&zb,  g_zb);
    cudaGetSymbolAddress((void**)&dinvp, g_dinv);
    cudaGetSymbolAddress((void**)&cntp, g_cnt);
    cudaGetSymbolAddress((void**)&hh,  g_hh);
    cudaGetSymbolAddress((void**)&hl,  g_hl);
    cudaGetSymbolAddress((void**)&Mh,  g_Mh);
    cudaGetSymbolAddress((void**)&Ml,  g_Ml);

    cudaFuncSetAttribute(k_gemm_mma, cudaFuncAttributeMaxDynamicSharedMemorySize,
                         SM_TOTAL);
    cudaFuncSetAttribute(k_mm128p, cudaFuncAttributeMaxDynamicSharedMemorySize,
                         FD * FD * 4);
    cudaFuncSetAttribute(k_uchain, cudaFuncAttributeMaxDynamicSharedMemorySize,
                         2 * FD * FD * 4);

    const int nb = (n + CHUNK - 1) / CHUNK;
    const int nhb = (n + 15) / 16;   // 16 nodes per 256-thread block

    // degree + normalization + CSR build (dinv fused into scan1)
    cudaMemsetAsync(cntp, 0, (size_t)n * sizeof(int));
    k_deg_count<<<(e + 255) / 256, 256>>>(dst, e);
    k_scan1    <<<nb, 256>>>(n);
    k_scan2    <<<1, 256>>>(nb, n);
    k_scan3    <<<nb, 256>>>(n);
    k_scatter  <<<(e + 255) / 256, 256>>>(src, dst, e);

    // weight chain (grid-parallel): W22 = W2^2, W4 = W22^2, M = W1*W4; split M
    k_mm128p<<<16, 256, FD * FD * 4>>>(W2,  W2,  W22);
    k_mm128p<<<16, 256, FD * FD * 4>>>(W22, W22, W4);
    k_mm128p<<<16, 256, FD * FD * 4>>>(W1,  W4,  M);
    k_wsplit<<<(FD * FD + 255) / 256, 256>>>(M, Mh, Ml);

    // fused bias-vector chain
    k_uchain<<<1, 128, 2 * FD * FD * 4>>>(W2, W4, b1, b2, uv);

    // X -> fp16 plane
    k_xhalf<<<(n * (FD / 4) + 255) / 256, 256>>>(x, n * (FD / 4));

    // 5 aggregation passes: Xh -> Ha -> Hb -> Ha -> Hb -> (hh,hl)
    k_aggH<0><<<nhb, 256>>>(Xh, dinvp, Ha, r1, za, n);
    k_aggH<1><<<nhb, 256>>>(Ha, za,    Hb, r2, zb, n);
    k_aggH<1><<<nhb, 256>>>(Hb, zb,    Ha, r3, za, n);
    k_aggH<1><<<nhb, 256>>>(Ha, za,    Hb, r4, zb, n);
    k_aggH<2><<<nhb, 256>>>(Hb, nullptr, nullptr, nullptr, nullptr, n);

    // final GEMM: out = Y*M + r1*u1 + r2*u2 + r3*u3 + r4*u4 + b2
    k_gemm_mma<<<GEMM_GRID, 256, SM_TOTAL>>>(hh, hl, Mh, Ml, out,
                                             r1, r2, r3, r4, uv, b2, n);
}

// round 17
// speedup vs baseline: 1.0508x; 1.0212x over previous
#include <cuda_runtime.h>
#include <cuda_bf16.h>
#include <cuda_fp16.h>
#include <stdint.h>

#define FD   128        // feature dim
#define MAXN 100000     // nodes
#define MAXE 1664000    // edges (1.6M + slack)
#define CHUNK 1024      // elements per scan block
#define TILE_M 128
#define SROW 136        // smem tile row stride in bf16 elems (272B, conflict-free)
#define SROWB (SROW * 2)
#define GEMM_GRID 148

// ---------------------------------------------------------------------------
// Scratch (device globals — no allocation allowed in kernel_launch)
// ---------------------------------------------------------------------------
__device__ float g_dinv[MAXN];
__device__ int   g_cnt  [MAXN];
__device__ int   g_rowptr[MAXN + 1];
__device__ int   g_fill [MAXN];
__device__ int   g_csrc [MAXE];
__device__ int   g_bsum [256];
__device__ int   g_boff [256];
__device__ float g_r1[MAXN], g_r2[MAXN], g_r3[MAXN], g_r4[MAXN];
__device__ float g_za[MAXN], g_zb[MAXN];
// fp16 feature planes: X copy + double-buffered intermediates
__device__ __align__(128) __half g_Xh[(size_t)(MAXN + 256) * FD];
__device__ __align__(128) __half g_Ha[(size_t)(MAXN + 256) * FD];
__device__ __align__(128) __half g_Hb[(size_t)(MAXN + 256) * FD];
__device__ __align__(128) __nv_bfloat16 g_hh[(size_t)(MAXN + 256) * FD];
__device__ __align__(128) __nv_bfloat16 g_hl[(size_t)(MAXN + 256) * FD];
__device__ __align__(128) float g_W22[FD * FD];
__device__ __align__(128) float g_W4 [FD * FD];
__device__ __align__(128) float g_M  [FD * FD];
__device__ __align__(128) __nv_bfloat16 g_Mh[FD * FD];
__device__ __align__(128) __nv_bfloat16 g_Ml[FD * FD];
__device__ float g_uv[4 * FD];   // u1,u2,u3,u4

// ---------------------------------------------------------------------------
// Degree counting
// ---------------------------------------------------------------------------
__global__ void k_deg_count(const int* __restrict__ dst, int e) {
    int i = blockIdx.x * blockDim.x + threadIdx.x;
    if (i < e) atomicAdd(&g_cnt[dst[i]], 1);
}

// ---------------------------------------------------------------------------
// 3-pass parallel exclusive scan of g_cnt -> g_rowptr / g_fill.
// Pass 1 also computes g_dinv (fused; both read g_cnt).
// ---------------------------------------------------------------------------
__global__ void __launch_bounds__(256) k_scan1(int n) {
    const int t = threadIdx.x;
    const int base = blockIdx.x * CHUNK + t * 4;
    int s = 0;
#pragma unroll
    for (int m = 0; m < 4; m++) {
        int i = base + m;
        if (i < n) {
            int cv = g_cnt[i];
            s += cv;
            g_dinv[i] = rsqrtf(2.0f + (float)cv);
        }
    }
#pragma unroll
    for (int o = 16; o > 0; o >>= 1) s += __shfl_down_sync(0xffffffffu, s, o);
    __shared__ int ws[8];
    if ((t & 31) == 0) ws[t >> 5] = s;
    __syncthreads();
    if (t < 8) {
        int v = ws[t];
#pragma unroll
        for (int o = 4; o > 0; o >>= 1) v += __shfl_down_sync(0xffu, v, o);
        if (t == 0) g_bsum[blockIdx.x] = v;
    }
}

__global__ void __launch_bounds__(256) k_scan2(int nb, int n) {
    __shared__ int sh[256];
    int t = threadIdx.x;
    int v = (t < nb) ? g_bsum[t] : 0;
    sh[t] = v;
    __syncthreads();
#pragma unroll
    for (int o = 1; o < 256; o <<= 1) {
        int u = (t >= o) ? sh[t - o] : 0;
        __syncthreads();
        sh[t] += u;
        __syncthreads();
    }
    g_boff[t] = sh[t] - v;
    if (t == nb - 1) g_rowptr[n] = sh[t];
}

__global__ void __launch_bounds__(256) k_scan3(int n) {
    const int t = threadIdx.x;
    const int lane = t & 31;
    const int warp = t >> 5;
    const int base = blockIdx.x * CHUNK + t * 4;

    int c[4];
    int s = 0;
#pragma unroll
    for (int m = 0; m < 4; m++) {
        int i = base + m;
        c[m] = (i < n) ? g_cnt[i] : 0;
        s += c[m];
    }
    int incl = s;
#pragma unroll
    for (int o = 1; o < 32; o <<= 1) {
        int u = __shfl_up_sync(0xffffffffu, incl, o);
        if (lane >= o) incl += u;
    }
    __shared__ int wtot[8];
    if (lane == 31) wtot[warp] = incl;
    __syncthreads();
    int woff = 0;
#pragma unroll
    for (int w = 0; w < 7; w++)
        if (w < warp) woff += wtot[w];
    int pre = g_boff[blockIdx.x] + woff + incl - s;
#pragma unroll
    for (int m = 0; m < 4; m++) {
        int i = base + m;
        if (i < n) {
            g_rowptr[i] = pre;
            g_fill[i]   = pre;
            pre += c[m];
        }
    }
}

__global__ void k_scatter(const int* __restrict__ src, const int* __restrict__ dst, int e) {
    int i = blockIdx.x * blockDim.x + threadIdx.x;
    if (i < e) {
        int d = dst[i];
        int pos = atomicAdd(&g_fill[d], 1);
        g_csrc[pos] = src[i];
    }
}

// ---------------------------------------------------------------------------
// Grid-parallel 128x128 matmul: C = A*B. grid=16 blocks, 8 rows/block.
// ---------------------------------------------------------------------------
__global__ void __launch_bounds__(256) k_mm128p(const float* __restrict__ A,
                                                const float* __restrict__ B,
                                                float* __restrict__ C) {
    extern __shared__ float sB[];   // [128][128]
    const int tid = threadIdx.x;
    for (int i = tid; i < FD * FD / 4; i += 256)
        ((float4*)sB)[i] = ((const float4*)B)[i];
    __syncthreads();
    const int row  = blockIdx.x * 8 + (tid >> 5);
    const int lane = tid & 31;
    float4 acc = make_float4(0.f, 0.f, 0.f, 0.f);
    const float* arow = A + row * FD;
#pragma unroll 4
    for (int k = 0; k < FD; k++) {
        float a = __ldg(arow + k);
        float4 b = ((const float4*)sB)[k * 32 + lane];
        acc.x = fmaf(a, b.x, acc.x);
        acc.y = fmaf(a, b.y, acc.y);
        acc.z = fmaf(a, b.z, acc.z);
        acc.w = fmaf(a, b.w, acc.w);
    }
    ((float4*)(C + row * FD))[lane] = acc;
}

// Fused bias-vector chain: u1=b2*W2, u2=u1*W2, u3=u2*W2, u4=b1*W4.
__global__ void __launch_bounds__(128) k_uchain(const float* __restrict__ W2,
                                                const float* __restrict__ W4,
                                                const float* __restrict__ b1,
                                                const float* __restrict__ b2,
                                                float* __restrict__ uv) {
    extern __shared__ float sm[];
    float* sW2 = sm;                 // 128*128
    float* sW4 = sm + FD * FD;       // 128*128
    __shared__ float su[FD];
    const int t = threadIdx.x;
    for (int i = t; i < FD * FD / 4; i += 128) {
        ((float4*)sW2)[i] = ((const float4*)W2)[i];
        ((float4*)sW4)[i] = ((const float4*)W4)[i];
    }
    su[t] = b2[t];
    __syncthreads();
#pragma unroll
    for (int rep = 0; rep < 3; rep++) {
        float s = 0.0f;
#pragma unroll 8
        for (int k = 0; k < FD; k++) s = fmaf(su[k], sW2[k * FD + t], s);
        __syncthreads();
        su[t] = s;
        uv[rep * FD + t] = s;
        __syncthreads();
    }
    su[t] = b1[t];
    __syncthreads();
    {
        float s = 0.0f;
#pragma unroll 8
        for (int k = 0; k < FD; k++) s = fmaf(su[k], sW4[k * FD + t], s);
        uv[3 * FD + t] = s;
    }
}

// M[k][n] fp32 -> Mh/Ml[n][k] bf16 (transposed: n rows, k contiguous)
__global__ void __launch_bounds__(256) k_wsplit(const float* __restrict__ W,
                                                __nv_bfloat16* __restrict__ Wh,
                                                __nv_bfloat16* __restrict__ Wl) {
    int i = blockIdx.x * blockDim.x + threadIdx.x;   // i = n*128 + k
    if (i >= FD * FD) return;
    int nn = i >> 7, kk = i & 127;
    float w = W[kk * FD + nn];
    __nv_bfloat16 h = __float2bfloat16_rn(w);
    __nv_bfloat16 l = __float2bfloat16_rn(w - __bfloat162float(h));
    Wh[i] = h;
    Wl[i] = l;
}

// X fp32 -> fp16 plane
__global__ void __launch_bounds__(256) k_xhalf(const float* __restrict__ x, int total4) {
    int i = blockIdx.x * blockDim.x + threadIdx.x;   // float4 index
    if (i >= total4) return;
    float4 v = *(const float4*)(x + (size_t)i * 4);
    __half2 h0 = __floats2half2_rn(v.x, v.y);
    __half2 h1 = __floats2half2_rn(v.z, v.w);
    uint2 p = make_uint2(*(uint32_t*)&h0, *(uint32_t*)&h1);
    *(uint2*)(g_Xh + (size_t)i * 4) = p;
}

// ---------------------------------------------------------------------------
// helpers: fp16 row chunk (8 cols) <-> 8 fp32; bf16 hi/lo split of 8 values
// ---------------------------------------------------------------------------
__device__ __forceinline__ void gather8(const __half* __restrict__ P,
                                        size_t base, int c, float* f) {
    uint4 p = *(const uint4*)(P + base + c);
    const __half2* h = (const __half2*)&p;
#pragma unroll
    for (int i = 0; i < 4; i++) {
        float2 t = __half22float2(h[i]);
        f[2 * i] = t.x; f[2 * i + 1] = t.y;
    }
}

__device__ __forceinline__ void store8(__half* __restrict__ P, size_t base,
                                       int c, const float* f) {
    uint4 p;
    __half2* h = (__half2*)&p;
#pragma unroll
    for (int i = 0; i < 4; i++) h[i] = __floats2half2_rn(f[2 * i], f[2 * i + 1]);
    *(uint4*)(P + base + c) = p;
}

__device__ __forceinline__ void split8(const float* v, uint4& hi, uint4& lo) {
    __nv_bfloat162* hp = (__nv_bfloat162*)&hi;
    __nv_bfloat162* lp = (__nv_bfloat162*)&lo;
#pragma unroll
    for (int i = 0; i < 4; i++) {
        float a = v[2 * i], b = v[2 * i + 1];
        __nv_bfloat16 ha = __float2bfloat16_rn(a);
        __nv_bfloat16 hb = __float2bfloat16_rn(b);
        __nv_bfloat16 la = __float2bfloat16_rn(a - __bfloat162float(ha));
        __nv_bfloat16 lb = __float2bfloat16_rn(b - __bfloat162float(hb));
        hp[i] = __halves2bfloat162(ha, hb);
        lp[i] = __halves2bfloat162(la, lb);
    }
}

// ---------------------------------------------------------------------------
// Linear aggregation passes: TWO nodes per warp (16 lanes x 16B per row),
// 4-deep register gather (R14 best-known shape).
// MODE 0 (PRE): In = Xh, src-weight dinv; out fp16; scalar chain z0=dinv
// MODE 1 (MID): In fp16; out fp16; scalar chain z_{k-1}
// MODE 2 (FIN): In fp16; out = bf16 hi/lo split (g_hh/g_hl)
// ---------------------------------------------------------------------------
template <int MODE>
__global__ void __launch_bounds__(256) k_aggH(const __half* __restrict__ In,
                                              const float* __restrict__ zin,
                                              __half* __restrict__ Out,
                                              float* __restrict__ rk,
                                              float* __restrict__ zout, int n) {
    const int node = blockIdx.x * 16 + (threadIdx.x >> 4);   // half-warp -> node
    const int lane = threadIdx.x & 15;
    const int c = lane << 3;                                  // 8 fp16 cols
    const bool act = (node < n);

    const int beg = act ? g_rowptr[node] : 0;
    const int end = act ? g_rowptr[node + 1] : 0;
    const float dv = act ? g_dinv[node] : 0.0f;

    float acc[8];
    if (act) {
        gather8(In, (size_t)node * FD, c, acc);
        const float sw = (MODE == 0) ? 2.0f * dv : 2.0f;
#pragma unroll
        for (int i = 0; i < 8; i++) acc[i] *= sw;
    } else {
#pragma unroll
        for (int i = 0; i < 8; i++) acc[i] = 0.0f;
    }
    float sacc = (MODE < 2 && act) ? 2.0f * __ldg(zin + node) : 0.0f;

    int j = beg;
    for (; j + 3 < end; j += 4) {
        int s0 = __ldg(g_csrc + j);
        int s1 = __ldg(g_csrc + j + 1);
        int s2 = __ldg(g_csrc + j + 2);
        int s3 = __ldg(g_csrc + j + 3);
        float v0[8], v1[8], v2[8], v3[8];
        gather8(In, (size_t)s0 * FD, c, v0);
        gather8(In, (size_t)s1 * FD, c, v1);
        gather8(In, (size_t)s2 * FD, c, v2);
        gather8(In, (size_t)s3 * FD, c, v3);
        if (MODE == 0) {
            float w0 = __ldg(zin + s0), w1 = __ldg(zin + s1);
            float w2 = __ldg(zin + s2), w3 = __ldg(zin + s3);
#pragma unroll
            for (int i = 0; i < 8; i++)
                acc[i] = fmaf(w0, v0[i], fmaf(w1, v1[i],
                          fmaf(w2, v2[i], fmaf(w3, v3[i], acc[i]))));
            sacc += w0 + w1 + w2 + w3;
        } else {
#pragma unroll
            for (int i = 0; i < 8; i++)
                acc[i] += (v0[i] + v1[i]) + (v2[i] + v3[i]);
            if (MODE == 1)
                sacc += __ldg(zin + s0) + __ldg(zin + s1)
                      + __ldg(zin + s2) + __ldg(zin + s3);
        }
    }
    for (; j < end; j++) {
        int s = __ldg(g_csrc + j);
        float v[8];
        gather8(In, (size_t)s * FD, c, v);
        if (MODE == 0) {
            float w = __ldg(zin + s);
#pragma unroll
            for (int i = 0; i < 8; i++) acc[i] = fmaf(w, v[i], acc[i]);
            sacc += w;
        } else {
#pragma unroll
            for (int i = 0; i < 8; i++) acc[i] += v[i];
            if (MODE == 1) sacc += __ldg(zin + s);
        }
    }

    if (!act) return;

    if (MODE == 2) {
#pragma unroll
        for (int i = 0; i < 8; i++) acc[i] *= dv;
        uint4 hi, lo;
        split8(acc, hi, lo);
        *(uint4*)(g_hh + (size_t)node * FD + c) = hi;
        *(uint4*)(g_hl + (size_t)node * FD + c) = lo;
    } else {
        const float s2 = dv * dv;
#pragma unroll
        for (int i = 0; i < 8; i++) acc[i] *= s2;
        store8(Out, (size_t)node * FD, c, acc);
        if (lane == 0) {
            rk[node]   = dv * sacc;
            zout[node] = s2 * sacc;
        }
    }
}

// ---------------------------------------------------------------------------
// Persistent HMMA GEMM with cp.async double buffering.
//   out = (Y @ M) + sum_k r_k (x) u_k + b2,  Y@M via bf16 3-term split
// ---------------------------------------------------------------------------
__device__ __forceinline__ uint32_t smem_to_u32(const void* p) {
    uint32_t a;
    asm("{ .reg .u64 t; cvta.to.shared.u64 t, %1; cvt.u32.u64 %0, t; }"
        : "=r"(a) : "l"(p));
    return a;
}

__device__ __forceinline__ void ldsm_x4(uint32_t& r0, uint32_t& r1,
                                        uint32_t& r2, uint32_t& r3, uint32_t addr) {
    asm volatile("ldmatrix.sync.aligned.m8n8.x4.shared.b16 {%0,%1,%2,%3}, [%4];"
                 : "=r"(r0), "=r"(r1), "=r"(r2), "=r"(r3) : "r"(addr));
}

__device__ __forceinline__ void mma16816(float* c, uint32_t a0, uint32_t a1,
                                         uint32_t a2, uint32_t a3,
                                         uint32_t b0, uint32_t b1) {
    asm volatile(
        "mma.sync.aligned.m16n8k16.row.col.f32.bf16.bf16.f32 "
        "{%0,%1,%2,%3}, {%4,%5,%6,%7}, {%8,%9}, {%0,%1,%2,%3};"
        : "+f"(c[0]), "+f"(c[1]), "+f"(c[2]), "+f"(c[3])
        : "r"(a0), "r"(a1), "r"(a2), "r"(a3), "r"(b0), "r"(b1));
}

__device__ __forceinline__ void cp_tile(uint32_t dstbase, const __nv_bfloat16* g) {
    const char* gp = (const char*)g;
    const int tid = threadIdx.x;
#pragma unroll
    for (int i = 0; i < 8; i++) {
        int gi = tid + i * 256;
        int r  = gi >> 4;
        int ch = gi & 15;
        uint32_t dst = dstbase + (uint32_t)r * SROWB + (uint32_t)ch * 16;
        asm volatile("cp.async.cg.shared.global [%0], [%1], 16;"
                     :: "r"(dst), "l"(gp + (size_t)gi * 16));
    }
}

#define CP_COMMIT() asm volatile("cp.async.commit_group;" ::: "memory")
template <int N>
__device__ __forceinline__ void cp_wait() {
    asm volatile("cp.async.wait_group %0;" :: "n"(N) : "memory");
}

#define TILEB  (128 * SROWB)
#define SM_WH  0
#define SM_WL  TILEB
#define SM_A0H (2 * TILEB)
#define SM_A0L (3 * TILEB)
#define SM_A1H (4 * TILEB)
#define SM_A1L (5 * TILEB)
#define SM_UVEC (6 * TILEB)
#define SM_TOTAL (6 * TILEB + 5 * FD * 4)

__global__ void __launch_bounds__(256, 1)
k_gemm_mma(const __nv_bfloat16* __restrict__ Ah,
           const __nv_bfloat16* __restrict__ Al,
           const __nv_bfloat16* __restrict__ Wh,
           const __nv_bfloat16* __restrict__ Wl,
           float* __restrict__ Out,
           const float* __restrict__ R1, const float* __restrict__ R2,
           const float* __restrict__ R3, const float* __restrict__ R4,
           const float* __restrict__ uv, const float* __restrict__ b2, int n) {
    extern __shared__ char smem[];
    const uint32_t sb = smem_to_u32(smem);
    float* su = (float*)(smem + SM_UVEC);   // u1,u2,u3,u4,b2 (5 x 128)
    const int tid  = threadIdx.x;
    const int lane = tid & 31;
    const int wr0  = (tid >> 5) << 4;
    const int ntiles = (n + TILE_M - 1) / TILE_M;

    if (tid < FD) {
#pragma unroll
        for (int t = 0; t < 4; t++) su[t * FD + tid] = uv[t * FD + tid];
        su[4 * FD + tid] = b2[tid];
    }

    const uint32_t aoff = (uint32_t)(wr0 + (lane & 15)) * SROWB
                        + (uint32_t)((lane >> 4) << 4);
    const uint32_t boff = (uint32_t)(((lane >> 4) << 3) + (lane & 7)) * SROWB
                        + (uint32_t)(((lane >> 3) & 1) << 4);

    int t0 = blockIdx.x;
    if (t0 >= ntiles) return;

    cp_tile(sb + SM_WH, Wh);
    cp_tile(sb + SM_WL, Wl);
    cp_tile(sb + SM_A0H, Ah + (size_t)t0 * TILE_M * FD);
    cp_tile(sb + SM_A0L, Al + (size_t)t0 * TILE_M * FD);
    CP_COMMIT();

    int stage = 0;
    for (int t = t0; t < ntiles; t += GEMM_GRID) {
        const int tn = t + GEMM_GRID;
        if (tn < ntiles) {
            const uint32_t dh = sb + (stage ? SM_A0H : SM_A1H);
            const uint32_t dl = sb + (stage ? SM_A0L : SM_A1L);
            cp_tile(dh, Ah + (size_t)tn * TILE_M * FD);
            cp_tile(dl, Al + (size_t)tn * TILE_M * FD);
            CP_COMMIT();
            cp_wait<1>();
        } else {
            cp_wait<0>();
        }
        __syncthreads();

        const uint32_t sAH = sb + (stage ? SM_A1H : SM_A0H);
        const uint32_t sAL = sb + (stage ? SM_A1L : SM_A0L);

        float acc[16][4];
#pragma unroll
        for (int q = 0; q < 16; q++)
#pragma unroll
            for (int j = 0; j < 4; j++) acc[q][j] = 0.0f;

#pragma unroll
        for (int term = 0; term < 3; term++) {
            const uint32_t aBase = aoff + ((term == 2) ? sAL : sAH);
            const uint32_t bBase = boff + sb + ((term == 1) ? SM_WL : SM_WH);

            uint32_t a[8][4];
#pragma unroll
            for (int ks = 0; ks < 8; ks++)
                ldsm_x4(a[ks][0], a[ks][1], a[ks][2], a[ks][3], aBase + ks * 32);

#pragma unroll
            for (int nt = 0; nt < 8; nt++) {
                const uint32_t bnt = bBase + (uint32_t)nt * 16 * SROWB;
#pragma unroll
                for (int ks = 0; ks < 8; ks++) {
                    uint32_t b0, b1, b2r, b3;
                    ldsm_x4(b0, b1, b2r, b3, bnt + ks * 32);
                    mma16816(acc[nt * 2],     a[ks][0], a[ks][1], a[ks][2], a[ks][3], b0, b1);
                    mma16816(acc[nt * 2 + 1], a[ks][0], a[ks][1], a[ks][2], a[ks][3], b2r, b3);
                }
            }
        }

        const int row0 = t * TILE_M;
        const int r0g = row0 + wr0 + (lane >> 2);
        const int r1g = r0g + 8;
        float ra[4] = {0.f, 0.f, 0.f, 0.f}, rb[4] = {0.f, 0.f, 0.f, 0.f};
        if (r0g < n) { ra[0] = R1[r0g]; ra[1] = R2[r0g]; ra[2] = R3[r0g]; ra[3] = R4[r0g]; }
        if (r1g < n) { rb[0] = R1[r1g]; rb[1] = R2[r1g]; rb[2] = R3[r1g]; rb[3] = R4[r1g]; }
        const int cbase = (lane & 3) << 1;
#pragma unroll
        for (int q = 0; q < 16; q++) {
            const int col = q * 8 + cbase;
            float e00 = acc[q][0], e01 = acc[q][1];
            float e10 = acc[q][2], e11 = acc[q][3];
#pragma unroll
            for (int k = 0; k < 4; k++) {
                float u0 = su[k * FD + col], u1 = su[k * FD + col + 1];
                e00 = fmaf(ra[k], u0, e00); e01 = fmaf(ra[k], u1, e01);
                e10 = fmaf(rb[k], u0, e10); e11 = fmaf(rb[k], u1, e11);
            }
            e00 += su[4 * FD + col]; e01 += su[4 * FD + col + 1];
            e10 += su[4 * FD + col]; e11 += su[4 * FD + col + 1];
            if (r0g < n)
                *(float2*)(Out + (size_t)r0g * FD + col) = make_float2(e00, e01);
            if (r1g < n)
                *(float2*)(Out + (size_t)r1g * FD + col) = make_float2(e10, e11);
        }

        __syncthreads();
        stage ^= 1;
    }
}

// ---------------------------------------------------------------------------
// Launcher
// ---------------------------------------------------------------------------
extern "C" void kernel_launch(void* const* d_in, const int* in_sizes, int n_in,
                              void* d_out, int out_size) {
    const float* x  = (const float*)d_in[0];
    const int*   ei = (const int*)  d_in[1];
    const float* W1 = (const float*)d_in[2];
    const float* b1 = (const float*)d_in[3];
    const float* W2 = (const float*)d_in[4];
    const float* b2 = (const float*)d_in[5];
    float* out = (float*)d_out;

    const int n = in_sizes[0] / FD;
    const int e = in_sizes[1] / 2;
    const int* src = ei;
    const int* dst = ei + e;

    float *W22, *W4, *M, *uv, *r1, *r2, *r3, *r4, *za, *zb, *dinvp;
    int* cntp;
    __half *Xh, *Ha, *Hb;
    __nv_bfloat16 *hh, *hl, *Mh, *Ml;
    cudaGetSymbolAddress((void**)&Xh,  g_Xh);
    cudaGetSymbolAddress((void**)&Ha,  g_Ha);
    cudaGetSymbolAddress((void**)&Hb,  g_Hb);
    cudaGetSymbolAddress((void**)&W22, g_W22);
    cudaGetSymbolAddress((void**)&W4,  g_W4);
    cudaGetSymbolAddress((void**)&M,   g_M);
    cudaGetSymbolAddress((void**)&uv,  g_uv);
    cudaGetSymbolAddress((void**)&r1,  g_r1);
    cudaGetSymbolAddress((void**)&r2,  g_r2);
    cudaGetSymbolAddress((void**)&r3,  g_r3);
    cudaGetSymbolAddress((void**)&r4,  g_r4);
    cudaGetSymbolAddress((void**)&za,  g_za);
    cudaGetSymbolAddress((void**)&zb,  g_zb);
    cudaGetSymbolAddress((void**)&dinvp, g_dinv);
    cudaGetSymbolAddress((void**)&cntp, g_cnt);
    cudaGetSymbolAddress((void**)&hh,  g_hh);
    cudaGetSymbolAddress((void**)&hl,  g_hl);
    cudaGetSymbolAddress((void**)&Mh,  g_Mh);
    cudaGetSymbolAddress((void**)&Ml,  g_Ml);

    cudaFuncSetAttribute(k_gemm_mma, cudaFuncAttributeMaxDynamicSharedMemorySize,
                         SM_TOTAL);
    cudaFuncSetAttribute(k_mm128p, cudaFuncAttributeMaxDynamicSharedMemorySize,
                         FD * FD * 4);
    cudaFuncSetAttribute(k_uchain, cudaFuncAttributeMaxDynamicSharedMemorySize,
                         2 * FD * FD * 4);

    const int nb = (n + CHUNK - 1) / CHUNK;
    const int nhb = (n + 15) / 16;   // 16 nodes per 256-thread block

    // degree + normalization + CSR build (dinv fused into scan1)
    cudaMemsetAsync(cntp, 0, (size_t)n * sizeof(int));
    k_deg_count<<<(e + 255) / 256, 256>>>(dst, e);
    k_scan1    <<<nb, 256>>>(n);
    k_scan2    <<<1, 256>>>(nb, n);
    k_scan3    <<<nb, 256>>>(n);
    k_scatter  <<<(e + 255) / 256, 256>>>(src, dst, e);

    // weight chain (grid-parallel): W22 = W2^2, W4 = W22^2, M = W1*W4; split M
    k_mm128p<<<16, 256, FD * FD * 4>>>(W2,  W2,  W22);
    k_mm128p<<<16, 256, FD * FD * 4>>>(W22, W22, W4);
    k_mm128p<<<16, 256, FD * FD * 4>>>(W1,  W4,  M);
    k_wsplit<<<(FD * FD + 255) / 256, 256>>>(M, Mh, Ml);

    // fused bias-vector chain
    k_uchain<<<1, 128, 2 * FD * FD * 4>>>(W2, W4, b1, b2, uv);

    // X -> fp16 plane
    k_xhalf<<<(n * (FD / 4) + 255) / 256, 256>>>(x, n * (FD / 4));

    // 5 aggregation passes: Xh -> Ha -> Hb -> Ha -> Hb -> (hh,hl)
    k_aggH<0><<<nhb, 256>>>(Xh, dinvp, Ha, r1, za, n);
    k_aggH<1><<<nhb, 256>>>(Ha, za,    Hb, r2, zb, n);
    k_aggH<1><<<nhb, 256>>>(Hb, zb,    Ha, r3, za, n);
    k_aggH<1><<<nhb, 256>>>(Ha, za,    Hb, r4, zb, n);
    k_aggH<2><<<nhb, 256>>>(Hb, nullptr, nullptr, nullptr, nullptr, n);

    // final GEMM: out = Y*M + r1*u1 + r2*u2 + r3*u3 + r4*u4 + b2
    k_gemm_mma<<<GEMM_GRID, 256, SM_TOTAL>>>(hh, hl, Mh, Ml, out,
                                             r1, r2, r3, r4, uv, b2, n);
}